// round 15
// baseline (speedup 1.0000x reference)
#include <cuda_runtime.h>
#include <cuda_fp16.h>
#include <math.h>
#include <stdint.h>
#include <string.h>

// ---------------- problem dims ----------------
#define NTOK 4096
#define CDIM 1024
#define HD 64
#define LAT 512
#define NEXP 8
#define FDIM 1024
#define FSH 2048
#define MAXSLOT 9216

// ---------------- scratch ----------------
__device__ __half g_xn_h [NTOK*CDIM];
__device__ __half g_q_h  [NTOK*CDIM];      // pre-scaled by 0.125
__device__ __half g_kv_h [NTOK*LAT];
__device__ __half g_kvo_h[NTOK*128];       // K|V interleaved per row
__device__ __half g_att_h[NTOK*CDIM];
__device__ float  g_h    [NTOK*CDIM];
__device__ float  g_hnf  [NTOK*CDIM];      // full fp32 (router only)
__device__ __half g_hn_h [NTOK*CDIM];      // half (MoE GEMM operand)
__device__ int    g_top[NTOK*2];
__device__ float  g_topw[NTOK*2];
__device__ int    g_tok_of_slot[MAXSLOT];
__device__ float  g_w_of_slot[MAXSLOT];
__device__ int    g_slot_of_tok[NTOK*2];
__device__ int    g_off_pad[NEXP];
__device__ int    g_cnt_pad[NEXP];
__device__ __half g_hid_h [MAXSLOT*FDIM];
__device__ float  g_ctb   [MAXSLOT*CDIM];
__device__ __half g_shid_h[NTOK*FSH];

// half weights, transposed to [N][K]
__device__ __half g_wqkv_h[1536*CDIM];
__device__ __half g_wkv_h [128*LAT];
__device__ __half g_wo_h  [CDIM*CDIM];
__device__ __half g_sw1_h[FSH*CDIM];
__device__ __half g_sw3_h[FSH*CDIM];
__device__ __half g_sw2_h[CDIM*FSH];
__device__ __half g_ew1_h[NEXP*FDIM*CDIM];
__device__ __half g_ew3_h[NEXP*FDIM*CDIM];
__device__ __half g_ew2_h[NEXP*CDIM*FDIM];

// ---------------- helpers ----------------
__device__ __forceinline__ float siluf(float x) { return x / (1.0f + expf(-x)); }

__device__ __forceinline__ unsigned h2_as_u32(__half2 h) {
    unsigned u;
    memcpy(&u, &h, 4);
    return u;
}

__device__ __forceinline__ uint32_t smem_u32(const void* p) {
    uint32_t a;
    asm("{ .reg .u64 t; cvta.to.shared.u64 t, %1; cvt.u32.u64 %0, t; }" : "=r"(a) : "l"(p));
    return a;
}
__device__ __forceinline__ void cpa16(uint32_t saddr, const void* g) {
    asm volatile("cp.async.cg.shared.global [%0], [%1], 16;" :: "r"(saddr), "l"(g));
}
#define CP_COMMIT() asm volatile("cp.async.commit_group;" ::: "memory")
#define CP_WAIT2()  asm volatile("cp.async.wait_group 2;" ::: "memory")

#define MMA_F16(d, a, b) asm volatile( \
  "mma.sync.aligned.m16n8k16.row.col.f32.f16.f16.f32 " \
  "{%0,%1,%2,%3}, {%4,%5,%6,%7}, {%8,%9}, {%0,%1,%2,%3};" \
  : "+f"(d[0]), "+f"(d[1]), "+f"(d[2]), "+f"(d[3]) \
  : "r"(a[0]), "r"(a[1]), "r"(a[2]), "r"(a[3]), "r"(b[0]), "r"(b[1]))

__device__ __forceinline__ float block_reduce_sum256(float v) {
    __shared__ float sm[8];
    __syncthreads();
    int lane = threadIdx.x & 31, w = threadIdx.x >> 5;
    #pragma unroll
    for (int o = 16; o; o >>= 1) v += __shfl_xor_sync(0xffffffffu, v, o);
    if (lane == 0) sm[w] = v;
    __syncthreads();
    float r = (threadIdx.x < 8) ? sm[threadIdx.x] : 0.0f;
    if (w == 0) {
        #pragma unroll
        for (int o = 4; o; o >>= 1) r += __shfl_xor_sync(0xffffffffu, r, o);
        if (lane == 0) sm[0] = r;
    }
    __syncthreads();
    return sm[0];
}

// ---------------- weight prep: src [R][C] fp32 (batched by z) -> dst [C][R] half --
__global__ __launch_bounds__(256)
void k_cvt_tr(const float* __restrict__ S, __half* __restrict__ D, int R, int C)
{
    __shared__ float t[32][33];
    size_t so = (size_t)blockIdx.z * R * C;
    int c0 = blockIdx.x * 32, r0 = blockIdx.y * 32;
    int tx = threadIdx.x & 31, ty = threadIdx.x >> 5;
    #pragma unroll
    for (int i = 0; i < 4; i++)
        t[ty + i*8][tx] = S[so + (size_t)(r0 + ty + i*8) * C + c0 + tx];
    __syncthreads();
    #pragma unroll
    for (int i = 0; i < 4; i++)
        D[so + (size_t)(c0 + ty + i*8) * R + r0 + tx] = __float2half_rn(t[tx][ty + i*8]);
}

// ---------------- fp16 cp.async GEMM (4-stage pipeline) ----------------
enum { HP_DUAL = 0, HP_EXPDUAL = 1, HP_EXPDOWN = 2, HP_RESID = 3, HP_QKV = 4, HP_HALF = 5, HP_FINAL = 6 };
#define SMHP 81920

template<int MODE, int BN>
__global__ __launch_bounds__(256)
void gemm_hp(const __half* __restrict__ Aa, int lda,
             const __half* __restrict__ B1a, const __half* __restrict__ B3a,
             void* __restrict__ Cv, int ldc,
             const float* __restrict__ Da, int K)
{
    constexpr bool DUAL = (MODE == HP_DUAL || MODE == HP_EXPDUAL);
    constexpr int NT  = BN / 16;
    constexpr int BCH = BN / 64;
    extern __shared__ __half hsm[];
    __half* sA  = hsm;                       // 4 x [128][40]
    __half* sB1 = hsm + 4 * 128 * 40;        // 4 x [BN][40]
    __half* sB3 = sB1 + (DUAL ? 4 * BN * 40 : 0);

    const int tid = threadIdx.x;
    const int nb = blockIdx.x, mb = blockIdx.y, z = blockIdx.z;
    const int m0 = mb * 128, n0 = nb * BN;

    const __half* A = Aa; const __half* B1 = B1a; const __half* B3 = B3a;
    const float* wrow = nullptr; const int* ridx = nullptr;
    void* C = Cv; int ldcx = ldc;

    if (MODE == HP_EXPDUAL) {
        if (m0 >= g_cnt_pad[z]) return;
        int off = g_off_pad[z];
        ridx = g_tok_of_slot + off;
        A = g_hn_h; lda = CDIM;
        B1 = B1a + (size_t)z * FDIM * CDIM;
        B3 = B3a + (size_t)z * FDIM * CDIM;
        C = (void*)(g_hid_h + (size_t)off * FDIM); ldcx = FDIM;
    } else if (MODE == HP_EXPDOWN) {
        if (m0 >= g_cnt_pad[z]) return;
        int off = g_off_pad[z];
        A = g_hid_h + (size_t)off * FDIM; lda = FDIM;
        B1 = B1a + (size_t)z * CDIM * FDIM;
        C = (void*)(g_ctb + (size_t)off * CDIM); ldcx = CDIM;
        wrow = g_w_of_slot + off;
    }

    const int lane = tid & 31, warp = tid >> 5;
    const int wm = warp & 3, wn = warp >> 2;
    const int mw = wm * 32, nw = wn * (BN / 2);
    const int grp = lane >> 2, tig = lane & 3;

    const int KT = K >> 5;

    auto ISSUE = [&](int kt, int st) {
        if (kt < KT) {
            int k0 = kt << 5;
            #pragma unroll
            for (int t = 0; t < 2; t++) {
                int c = tid + 256 * t;
                int row = c >> 2, q = c & 3;
                int gr = (MODE == HP_EXPDUAL) ? ridx[m0 + row] : (m0 + row);
                cpa16(smem_u32(&sA[st * 128 * 40 + row * 40 + q * 8]),
                      A + (size_t)gr * lda + k0 + q * 8);
            }
            #pragma unroll
            for (int t = 0; t < BCH; t++) {
                int c = tid + 256 * t;
                int row = c >> 2, q = c & 3;
                cpa16(smem_u32(&sB1[st * BN * 40 + row * 40 + q * 8]),
                      B1 + (size_t)(n0 + row) * K + k0 + q * 8);
                if (DUAL)
                    cpa16(smem_u32(&sB3[st * BN * 40 + row * 40 + q * 8]),
                          B3 + (size_t)(n0 + row) * K + k0 + q * 8);
            }
        }
        CP_COMMIT();
    };

    float acc1[2][NT][4] = {};
    float acc3[2][DUAL ? NT : 1][4] = {};

    auto COMP = [&](int st) {
        const unsigned* uA  = (const unsigned*)(sA  + st * 128 * 40);
        const unsigned* uB1 = (const unsigned*)(sB1 + st * BN * 40);
        const unsigned* uB3 = (const unsigned*)(sB3 + st * BN * 40);
        #pragma unroll
        for (int s16 = 0; s16 < 2; s16++) {
            int ko = s16 * 8;
            unsigned bF1[NT][2], bF3[DUAL ? NT : 1][2], aF[2][4];
            #pragma unroll
            for (int j = 0; j < NT; j++) {
                int n = nw + j * 8 + grp;
                bF1[j][0] = uB1[n * 20 + ko + tig];
                bF1[j][1] = uB1[n * 20 + ko + 4 + tig];
                if (DUAL) {
                    bF3[j][0] = uB3[n * 20 + ko + tig];
                    bF3[j][1] = uB3[n * 20 + ko + 4 + tig];
                }
            }
            #pragma unroll
            for (int i = 0; i < 2; i++) {
                int m = mw + i * 16 + grp;
                aF[i][0] = uA[m * 20 + ko + tig];
                aF[i][1] = uA[(m + 8) * 20 + ko + tig];
                aF[i][2] = uA[m * 20 + ko + 4 + tig];
                aF[i][3] = uA[(m + 8) * 20 + ko + 4 + tig];
            }
            #pragma unroll
            for (int i = 0; i < 2; i++)
                #pragma unroll
                for (int j = 0; j < NT; j++) {
                    MMA_F16(acc1[i][j], aF[i], bF1[j]);
                    if (DUAL) MMA_F16(acc3[i][j], aF[i], bF3[j]);
                }
        }
    };

    ISSUE(0, 0);
    ISSUE(1, 1);
    ISSUE(2, 2);
    for (int kt = 0; kt < KT; kt++) {
        int st = kt & 3;
        CP_WAIT2();
        __syncthreads();
        ISSUE(kt + 3, (kt + 3) & 3);
        COMP(st);
    }

    #pragma unroll
    for (int i = 0; i < 2; i++) {
        #pragma unroll
        for (int j = 0; j < NT; j++) {
            #pragma unroll
            for (int hh = 0; hh < 2; hh++) {
                int ml = mw + i * 16 + grp + hh * 8;
                int nl = nw + j * 8 + 2 * tig;
                float v0 = acc1[i][j][hh * 2 + 0];
                float v1 = acc1[i][j][hh * 2 + 1];
                int gm = m0 + ml, gn = n0 + nl;
                if (DUAL) {
                    v0 = v0 * siluf(acc3[i][j][hh * 2 + 0]);
                    v1 = v1 * siluf(acc3[i][j][hh * 2 + 1]);
                    *(__half2*)((__half*)C + (size_t)gm * ldcx + gn) = __floats2half2_rn(v0, v1);
                } else if (MODE == HP_EXPDOWN) {
                    float w = wrow[gm];
                    *(float2*)((float*)C + (size_t)gm * ldcx + gn) = make_float2(v0 * w, v1 * w);
                } else if (MODE == HP_RESID) {
                    float2 d = *(const float2*)(Da + (size_t)gm * ldcx + gn);
                    *(float2*)((float*)C + (size_t)gm * ldcx + gn) = make_float2(v0 + d.x, v1 + d.y);
                } else if (MODE == HP_FINAL) {
                    // out = ((acc + hb) + ctb[s0]) + ctb[s1]  (same order as separate combine)
                    int s0 = g_slot_of_tok[gm * 2];
                    int s1 = g_slot_of_tok[gm * 2 + 1];
                    float2 d  = *(const float2*)(Da + (size_t)gm * ldcx + gn);
                    float2 c0 = *(const float2*)(g_ctb + (size_t)s0 * CDIM + gn);
                    float2 c1 = *(const float2*)(g_ctb + (size_t)s1 * CDIM + gn);
                    float o0 = ((v0 + d.x) + c0.x) + c1.x;
                    float o1 = ((v1 + d.y) + c0.y) + c1.y;
                    *(float2*)((float*)C + (size_t)gm * ldcx + gn) = make_float2(o0, o1);
                } else if (MODE == HP_QKV) {
                    if (gn < 1024)
                        *(__half2*)(g_q_h + (size_t)gm * 1024 + gn) =
                            __floats2half2_rn(v0 * 0.125f, v1 * 0.125f);
                    else
                        *(__half2*)(g_kv_h + (size_t)gm * 512 + gn - 1024) =
                            __floats2half2_rn(v0, v1);
                } else {  // HP_HALF
                    *(__half2*)((__half*)C + (size_t)gm * ldcx + gn) = __floats2half2_rn(v0, v1);
                }
            }
        }
    }
}

// ---------------- fp16 flash attention (online softmax) ----------------
#define FA_BYTES 91136

__global__ __launch_bounds__(256)
void k_flash_h(const __half* __restrict__ Qg, const __half* __restrict__ KVg,
               __half* __restrict__ Og)
{
    extern __shared__ __half fh[];
    __half* sQ  = fh;            // [128][72]
    __half* sK  = fh + 9216;     // [128][72]
    __half* sVt = fh + 18432;    // [64][136]  V transposed [d][s]
    __half* sP  = fh + 27136;    // [128][136]
    float* sRM = (float*)(fh + 44544);
    float* sRS = sRM + 256;
    const unsigned* uQ  = (const unsigned*)sQ;
    const unsigned* uK  = (const unsigned*)sK;
    const unsigned* uVt = (const unsigned*)sVt;
    unsigned* uP = (unsigned*)sP;

    const int qt = blockIdx.x, bh = blockIdx.y;
    const int b = bh >> 4, hh = bh & 15;
    const int tid = threadIdx.x, warp = tid >> 5, lane = tid & 31;
    const int wm = warp & 3, wn = warp >> 2;
    const int grp = lane >> 2, tig = lane & 3;
    const float NEG = -1e30f;

    const __half* Qb = Qg + (size_t)(b*1024 + qt*128) * 1024 + hh*64;
    #pragma unroll
    for (int t = 0; t < 4; t++) {
        int idx = tid + t*256;
        int r = idx >> 3, c = idx & 7;
        *(uint4*)&sQ[r*72 + c*8] = *(const uint4*)(Qb + (size_t)r*1024 + c*8);
    }

    float m_i[2][2] = {{NEG,NEG},{NEG,NEG}};
    float l_i[2][2] = {{0.f,0.f},{0.f,0.f}};
    float oacc[2][4][4] = {};

    for (int kt = 0; kt <= qt; kt++) {
        __syncthreads();
        const __half* KVb = KVg + (size_t)(b*1024 + kt*128) * 128;
        #pragma unroll
        for (int t = 0; t < 4; t++) {
            int idx = tid + t*256;
            int r = idx >> 3, c = idx & 7;
            *(uint4*)&sK[r*72 + c*8] = *(const uint4*)(KVb + (size_t)r*128 + c*8);
            uint4 vv = *(const uint4*)(KVb + (size_t)r*128 + 64 + c*8);
            __half tmp[8];
            memcpy(tmp, &vv, 16);
            #pragma unroll
            for (int i = 0; i < 8; i++)
                sVt[(c*8 + i)*136 + r] = tmp[i];
        }
        __syncthreads();

        float sacc[2][8][4] = {};
        #pragma unroll
        for (int ks = 0; ks < 4; ks++) {
            int ko = ks * 8;
            unsigned aF[2][4], bF[8][2];
            #pragma unroll
            for (int j = 0; j < 8; j++) {
                int n = wn*64 + j*8 + grp;
                bF[j][0] = uK[n*36 + ko + tig];
                bF[j][1] = uK[n*36 + ko + 4 + tig];
            }
            #pragma unroll
            for (int i = 0; i < 2; i++) {
                int m = wm*32 + i*16 + grp;
                aF[i][0] = uQ[m*36 + ko + tig];
                aF[i][1] = uQ[(m+8)*36 + ko + tig];
                aF[i][2] = uQ[m*36 + ko + 4 + tig];
                aF[i][3] = uQ[(m+8)*36 + ko + 4 + tig];
            }
            #pragma unroll
            for (int i = 0; i < 2; i++)
                #pragma unroll
                for (int j = 0; j < 8; j++)
                    MMA_F16(sacc[i][j], aF[i], bF[j]);
        }

        if (kt == qt) {
            #pragma unroll
            for (int i = 0; i < 2; i++)
                #pragma unroll
                for (int h2 = 0; h2 < 2; h2++) {
                    int row = wm*32 + i*16 + grp + h2*8;
                    #pragma unroll
                    for (int j = 0; j < 8; j++) {
                        int col = wn*64 + j*8 + 2*tig;
                        if (col   > row) sacc[i][j][h2*2]   = NEG;
                        if (col+1 > row) sacc[i][j][h2*2+1] = NEG;
                    }
                }
        }

        #pragma unroll
        for (int i = 0; i < 2; i++)
            #pragma unroll
            for (int h2 = 0; h2 < 2; h2++) {
                float v = NEG;
                #pragma unroll
                for (int j = 0; j < 8; j++)
                    v = fmaxf(v, fmaxf(sacc[i][j][h2*2], sacc[i][j][h2*2+1]));
                v = fmaxf(v, __shfl_xor_sync(0xffffffffu, v, 1));
                v = fmaxf(v, __shfl_xor_sync(0xffffffffu, v, 2));
                if (tig == 0) sRM[wn*128 + wm*32 + i*16 + grp + h2*8] = v;
            }
        __syncthreads();

        #pragma unroll
        for (int i = 0; i < 2; i++)
            #pragma unroll
            for (int h2 = 0; h2 < 2; h2++) {
                int row = wm*32 + i*16 + grp + h2*8;
                float mnew = fmaxf(m_i[i][h2], fmaxf(sRM[row], sRM[128+row]));
                float fac = __expf(m_i[i][h2] - mnew);
                m_i[i][h2] = mnew;
                l_i[i][h2] *= fac;
                #pragma unroll
                for (int j = 0; j < 4; j++) {
                    oacc[i][j][h2*2]   *= fac;
                    oacc[i][j][h2*2+1] *= fac;
                }
                float rs = 0.0f;
                #pragma unroll
                for (int j = 0; j < 8; j++) {
                    float p0 = __expf(sacc[i][j][h2*2]   - mnew);
                    float p1 = __expf(sacc[i][j][h2*2+1] - mnew);
                    rs += p0 + p1;
                    int cu = wn*32 + j*4 + tig;
                    uP[row*68 + cu] = h2_as_u32(__floats2half2_rn(p0, p1));
                }
                rs += __shfl_xor_sync(0xffffffffu, rs, 1);
                rs += __shfl_xor_sync(0xffffffffu, rs, 2);
                if (tig == 0) sRS[wn*128 + row] = rs;
            }
        __syncthreads();
        #pragma unroll
        for (int i = 0; i < 2; i++)
            #pragma unroll
            for (int h2 = 0; h2 < 2; h2++) {
                int row = wm*32 + i*16 + grp + h2*8;
                l_i[i][h2] += sRS[row] + sRS[128 + row];
            }

        #pragma unroll
        for (int ks = 0; ks < 8; ks++) {
            int ko = ks * 8;
            unsigned aF[2][4], bF[4][2];
            #pragma unroll
            for (int j = 0; j < 4; j++) {
                int n = wn*32 + j*8 + grp;
                bF[j][0] = uVt[n*68 + ko + tig];
                bF[j][1] = uVt[n*68 + ko + 4 + tig];
            }
            #pragma unroll
            for (int i = 0; i < 2; i++) {
                int m = wm*32 + i*16 + grp;
                aF[i][0] = uP[m*68 + ko + tig];
                aF[i][1] = uP[(m+8)*68 + ko + tig];
                aF[i][2] = uP[m*68 + ko + 4 + tig];
                aF[i][3] = uP[(m+8)*68 + ko + 4 + tig];
            }
            #pragma unroll
            for (int i = 0; i < 2; i++)
                #pragma unroll
                for (int j = 0; j < 4; j++)
                    MMA_F16(oacc[i][j], aF[i], bF[j]);
        }
    }

    __half* Ob = Og + (size_t)(b*1024 + qt*128) * 1024 + hh*64;
    #pragma unroll
    for (int i = 0; i < 2; i++)
        #pragma unroll
        for (int h2 = 0; h2 < 2; h2++) {
            int row = wm*32 + i*16 + grp + h2*8;
            float inv = 1.0f / l_i[i][h2];
            #pragma unroll
            for (int j = 0; j < 4; j++) {
                int col = wn*32 + j*8 + 2*tig;
                *(__half2*)(Ob + (size_t)row*1024 + col) =
                    __floats2half2_rn(oacc[i][j][h2*2]*inv, oacc[i][j][h2*2+1]*inv);
            }
        }
}

// ---------------- elementwise / small kernels ----------------
__global__ __launch_bounds__(256)
void k_rmsnorm(const float* __restrict__ X, const float* __restrict__ G,
               float* __restrict__ Of, __half* __restrict__ Oh)
{
    int n = blockIdx.x;
    const float4* x4 = (const float4*)(X + (size_t)n * CDIM);
    const float4* g4 = (const float4*)G;
    float4 v = x4[threadIdx.x];
    float ss = v.x*v.x + v.y*v.y + v.z*v.z + v.w*v.w;
    float tot = block_reduce_sum256(ss);
    float r = 1.0f / sqrtf(tot * (1.0f / CDIM) + 1e-6f);
    float4 g = g4[threadIdx.x];
    float4 full = make_float4(v.x*r*g.x, v.y*r*g.y, v.z*r*g.z, v.w*r*g.w);
    if (Of) ((float4*)(Of + (size_t)n * CDIM))[threadIdx.x] = full;
    if (Oh) {
        *(__half2*)(Oh + (size_t)n * CDIM + threadIdx.x * 4)     = __floats2half2_rn(full.x, full.y);
        *(__half2*)(Oh + (size_t)n * CDIM + threadIdx.x * 4 + 2) = __floats2half2_rn(full.z, full.w);
    }
}

__global__ __launch_bounds__(128)
void k_router(const float* __restrict__ HN, const float* __restrict__ WR,
              const float* __restrict__ RB)
{
    int n = blockIdx.x * 4 + (threadIdx.x >> 5);
    int lane = threadIdx.x & 31;
    const float* x = HN + (size_t)n * CDIM;
    float p[NEXP] = {};
    for (int c = lane; c < CDIM; c += 32) {
        float xv = x[c];
        #pragma unroll
        for (int e = 0; e < NEXP; e++) p[e] += xv * WR[c * NEXP + e];
    }
    #pragma unroll
    for (int e = 0; e < NEXP; e++) {
        #pragma unroll
        for (int o = 16; o; o >>= 1)
            p[e] += __shfl_xor_sync(0xffffffffu, p[e], o);
    }
    if (lane == 0) {
        float logit[NEXP], biased[NEXP];
        #pragma unroll
        for (int e = 0; e < NEXP; e++) {
            logit[e]  = p[e] * 0.03125f;
            biased[e] = logit[e] + RB[e];
        }
        int i0 = 0;
        #pragma unroll
        for (int e = 1; e < NEXP; e++) if (biased[e] > biased[i0]) i0 = e;
        int i1 = -1;
        #pragma unroll
        for (int e = 0; e < NEXP; e++) {
            if (e == i0) continue;
            if (i1 < 0 || biased[e] > biased[i1]) i1 = e;
        }
        float m  = fmaxf(logit[i0], logit[i1]);
        float e0 = expf(logit[i0] - m), e1 = expf(logit[i1] - m);
        float inv = 1.0f / (e0 + e1);
        g_top [n*2]     = i0; g_top [n*2 + 1] = i1;
        g_topw[n*2]     = e0 * inv;
        g_topw[n*2 + 1] = e1 * inv;
    }
}

__global__ __launch_bounds__(256)
void k_place()
{
    __shared__ int cnt[NEXP], offp[NEXP], cntp[NEXP], cur[NEXP];
    int tid = threadIdx.x;
    if (tid < NEXP) cnt[tid] = 0;
    __syncthreads();
    for (int i = tid; i < NTOK * 2; i += 256) atomicAdd(&cnt[g_top[i]], 1);
    __syncthreads();
    if (tid == 0) {
        int o = 0;
        for (int e = 0; e < NEXP; e++) {
            offp[e] = o;
            cntp[e] = ((cnt[e] + 127) >> 7) << 7;
            cur[e]  = o;
            g_off_pad[e] = o;
            g_cnt_pad[e] = cntp[e];
            o += cntp[e];
        }
    }
    __syncthreads();
    for (int i = tid; i < NTOK * 2; i += 256) {
        int e = g_top[i];
        int s = atomicAdd(&cur[e], 1);
        g_tok_of_slot[s] = i >> 1;
        g_w_of_slot[s]   = g_topw[i];
        g_slot_of_tok[i] = s;
    }
    __syncthreads();
    for (int e = 0; e < NEXP; e++) {
        int start = offp[e] + cnt[e];
        int end   = offp[e] + cntp[e];
        for (int i = start + tid; i < end; i += 256) {
            g_tok_of_slot[i] = 0;
            g_w_of_slot[i]   = 0.0f;
        }
    }
}

// ---------------- launch ----------------
extern "C" void kernel_launch(void* const* d_in, const int* in_sizes, int n_in,
                              void* d_out, int out_size)
{
    const float* x    = (const float*)d_in[0];
    const float* ga   = (const float*)d_in[1];
    const float* wq   = (const float*)d_in[2];
    const float* wkvd = (const float*)d_in[3];
    const float* wku  = (const float*)d_in[4];
    const float* wvu  = (const float*)d_in[5];
    const float* wo   = (const float*)d_in[6];
    const float* gm   = (const float*)d_in[7];
    const float* wr   = (const float*)d_in[8];
    const float* rb   = (const float*)d_in[9];
    const float* ew1  = (const float*)d_in[10];
    const float* ew2  = (const float*)d_in[11];
    const float* ew3  = (const float*)d_in[12];
    const float* sw1  = (const float*)d_in[13];
    const float* sw2  = (const float*)d_in[14];
    const float* sw3  = (const float*)d_in[15];
    float* out = (float*)d_out;

    float *hb, *hnf;
    __half *xn_h, *q_h, *kv_h, *kvo_h, *att_h, *hn_h, *shid_h;
    __half *wqkv_h, *wkv_h, *wo_h, *sw1_h, *sw3_h, *sw2_h, *ew1_h, *ew2_h, *ew3_h;
    cudaGetSymbolAddress((void**)&hb,   g_h);
    cudaGetSymbolAddress((void**)&hnf,  g_hnf);
    cudaGetSymbolAddress((void**)&xn_h,  g_xn_h);
    cudaGetSymbolAddress((void**)&q_h,   g_q_h);
    cudaGetSymbolAddress((void**)&kv_h,  g_kv_h);
    cudaGetSymbolAddress((void**)&kvo_h, g_kvo_h);
    cudaGetSymbolAddress((void**)&att_h, g_att_h);
    cudaGetSymbolAddress((void**)&hn_h,  g_hn_h);
    cudaGetSymbolAddress((void**)&shid_h, g_shid_h);
    cudaGetSymbolAddress((void**)&wqkv_h, g_wqkv_h);
    cudaGetSymbolAddress((void**)&wkv_h,  g_wkv_h);
    cudaGetSymbolAddress((void**)&wo_h,   g_wo_h);
    cudaGetSymbolAddress((void**)&sw1_h,  g_sw1_h);
    cudaGetSymbolAddress((void**)&sw3_h,  g_sw3_h);
    cudaGetSymbolAddress((void**)&sw2_h,  g_sw2_h);
    cudaGetSymbolAddress((void**)&ew1_h,  g_ew1_h);
    cudaGetSymbolAddress((void**)&ew2_h,  g_ew2_h);
    cudaGetSymbolAddress((void**)&ew3_h,  g_ew3_h);

    cudaFuncSetAttribute(k_flash_h, cudaFuncAttributeMaxDynamicSharedMemorySize, FA_BYTES);
    cudaFuncSetAttribute(gemm_hp<HP_DUAL,64>,     cudaFuncAttributeMaxDynamicSharedMemorySize, SMHP);
    cudaFuncSetAttribute(gemm_hp<HP_EXPDUAL,64>,  cudaFuncAttributeMaxDynamicSharedMemorySize, SMHP);
    cudaFuncSetAttribute(gemm_hp<HP_EXPDOWN,128>, cudaFuncAttributeMaxDynamicSharedMemorySize, SMHP);
    cudaFuncSetAttribute(gemm_hp<HP_RESID,128>,   cudaFuncAttributeMaxDynamicSharedMemorySize, SMHP);
    cudaFuncSetAttribute(gemm_hp<HP_QKV,128>,     cudaFuncAttributeMaxDynamicSharedMemorySize, SMHP);
    cudaFuncSetAttribute(gemm_hp<HP_HALF,128>,    cudaFuncAttributeMaxDynamicSharedMemorySize, SMHP);
    cudaFuncSetAttribute(gemm_hp<HP_FINAL,128>,   cudaFuncAttributeMaxDynamicSharedMemorySize, SMHP);

    // ---- weight prep: convert + transpose to [N][K] half ----
    k_cvt_tr<<<dim3(32, 32), 256>>>(wq,   wqkv_h,             1024, 1024);
    k_cvt_tr<<<dim3(16, 32), 256>>>(wkvd, wqkv_h + 1024*1024, 1024, 512);
    k_cvt_tr<<<dim3(2, 16), 256>>>(wku,  wkv_h,              512,  64);
    k_cvt_tr<<<dim3(2, 16), 256>>>(wvu,  wkv_h + 64*512,     512,  64);
    k_cvt_tr<<<dim3(32, 32), 256>>>(wo,   wo_h,               1024, 1024);
    k_cvt_tr<<<dim3(32, 32, NEXP), 256>>>(ew1, ew1_h, CDIM, FDIM);
    k_cvt_tr<<<dim3(32, 32, NEXP), 256>>>(ew3, ew3_h, CDIM, FDIM);
    k_cvt_tr<<<dim3(32, 32, NEXP), 256>>>(ew2, ew2_h, FDIM, CDIM);
    k_cvt_tr<<<dim3(64, 32), 256>>>(sw1, sw1_h, CDIM, FSH);
    k_cvt_tr<<<dim3(64, 32), 256>>>(sw3, sw3_h, CDIM, FSH);
    k_cvt_tr<<<dim3(32, 64), 256>>>(sw2, sw2_h, FSH, CDIM);

    // ---- attention (fp16) ----
    k_rmsnorm<<<NTOK, 256>>>(x, ga, nullptr, xn_h);
    gemm_hp<HP_QKV,128><<<dim3(12, 32), 256, SMHP>>>(xn_h, 1024, wqkv_h, nullptr, nullptr, 0, nullptr, 1024);
    gemm_hp<HP_HALF,128><<<dim3(1, 32), 256, SMHP>>>(kv_h, 512, wkv_h, nullptr, kvo_h, 128, nullptr, 512);
    k_flash_h<<<dim3(8, 64), 256, FA_BYTES>>>(q_h, kvo_h, att_h);
    gemm_hp<HP_RESID,128><<<dim3(8, 32), 256, SMHP>>>(att_h, 1024, wo_h, nullptr, hb, 1024, x, 1024);

    // ---- MoE (fp16) ----
    k_rmsnorm<<<NTOK, 256>>>(hb, gm, hnf, hn_h);
    k_router<<<NTOK/4, 128>>>(hnf, wr, rb);
    k_place<<<1, 256>>>();
    gemm_hp<HP_EXPDUAL,64><<<dim3(16, 72, NEXP), 256, SMHP>>>(nullptr, 0, ew1_h, ew3_h, nullptr, 0, nullptr, 1024);
    gemm_hp<HP_EXPDOWN,128><<<dim3(8, 72, NEXP), 256, SMHP>>>(nullptr, 0, ew2_h, nullptr, nullptr, 0, nullptr, 1024);
    gemm_hp<HP_DUAL,64><<<dim3(32, 32), 256, SMHP>>>(hn_h, 1024, sw1_h, sw3_h, shid_h, 2048, nullptr, 1024);
    gemm_hp<HP_FINAL,128><<<dim3(8, 32), 256, SMHP>>>(shid_h, 2048, sw2_h, nullptr, out, 1024, hb, 2048);
}

// round 16
// speedup vs baseline: 1.0659x; 1.0659x over previous
#include <cuda_runtime.h>
#include <cuda_fp16.h>
#include <math.h>
#include <stdint.h>
#include <string.h>

// ---------------- problem dims ----------------
#define NTOK 4096
#define CDIM 1024
#define HD 64
#define LAT 512
#define NEXP 8
#define FDIM 1024
#define FSH 2048
#define MAXSLOT 9216

// ---------------- scratch ----------------
__device__ __half g_xn_h [NTOK*CDIM];
__device__ __half g_q_h  [NTOK*CDIM];      // pre-scaled by 0.125
__device__ __half g_kv_h [NTOK*LAT];
__device__ __half g_kvo_h[NTOK*128];       // K|V interleaved per row
__device__ __half g_att_h[NTOK*CDIM];
__device__ float  g_h    [NTOK*CDIM];
__device__ float  g_hnf  [NTOK*CDIM];      // full fp32 (router only)
__device__ __half g_hn_h [NTOK*CDIM];      // half (MoE GEMM operand)
__device__ int    g_top[NTOK*2];
__device__ float  g_topw[NTOK*2];
__device__ int    g_tok_of_slot[MAXSLOT];
__device__ float  g_w_of_slot[MAXSLOT];
__device__ int    g_slot_of_tok[NTOK*2];
__device__ int    g_off_pad[NEXP];
__device__ int    g_cnt_pad[NEXP];
__device__ __half g_hid_h [MAXSLOT*FDIM];
__device__ float  g_ctb   [MAXSLOT*CDIM];
__device__ __half g_shid_h[NTOK*FSH];

// half weights, transposed to [N][K]
__device__ __half g_wqkv_h[1536*CDIM];
__device__ __half g_wkv_h [128*LAT];
__device__ __half g_wo_h  [CDIM*CDIM];
__device__ __half g_sw1_h[FSH*CDIM];
__device__ __half g_sw3_h[FSH*CDIM];
__device__ __half g_sw2_h[CDIM*FSH];
__device__ __half g_ew1_h[NEXP*FDIM*CDIM];
__device__ __half g_ew3_h[NEXP*FDIM*CDIM];
__device__ __half g_ew2_h[NEXP*CDIM*FDIM];

// ---------------- helpers ----------------
__device__ __forceinline__ float siluf(float x) { return x / (1.0f + expf(-x)); }

__device__ __forceinline__ unsigned h2_as_u32(__half2 h) {
    unsigned u;
    memcpy(&u, &h, 4);
    return u;
}

__device__ __forceinline__ uint32_t smem_u32(const void* p) {
    uint32_t a;
    asm("{ .reg .u64 t; cvta.to.shared.u64 t, %1; cvt.u32.u64 %0, t; }" : "=r"(a) : "l"(p));
    return a;
}
__device__ __forceinline__ void cpa16(uint32_t saddr, const void* g) {
    asm volatile("cp.async.cg.shared.global [%0], [%1], 16;" :: "r"(saddr), "l"(g));
}
#define CP_COMMIT() asm volatile("cp.async.commit_group;" ::: "memory")
#define CP_WAIT1()  asm volatile("cp.async.wait_group 1;" ::: "memory")

#define MMA_F16(d, a, b) asm volatile( \
  "mma.sync.aligned.m16n8k16.row.col.f32.f16.f16.f32 " \
  "{%0,%1,%2,%3}, {%4,%5,%6,%7}, {%8,%9}, {%0,%1,%2,%3};" \
  : "+f"(d[0]), "+f"(d[1]), "+f"(d[2]), "+f"(d[3]) \
  : "r"(a[0]), "r"(a[1]), "r"(a[2]), "r"(a[3]), "r"(b[0]), "r"(b[1]))

__device__ __forceinline__ float block_reduce_sum256(float v) {
    __shared__ float sm[8];
    __syncthreads();
    int lane = threadIdx.x & 31, w = threadIdx.x >> 5;
    #pragma unroll
    for (int o = 16; o; o >>= 1) v += __shfl_xor_sync(0xffffffffu, v, o);
    if (lane == 0) sm[w] = v;
    __syncthreads();
    float r = (threadIdx.x < 8) ? sm[threadIdx.x] : 0.0f;
    if (w == 0) {
        #pragma unroll
        for (int o = 4; o; o >>= 1) r += __shfl_xor_sync(0xffffffffu, r, o);
        if (lane == 0) sm[0] = r;
    }
    __syncthreads();
    return sm[0];
}

// ---------------- weight prep: src [R][C] fp32 (batched by z) -> dst [C][R] half --
__global__ __launch_bounds__(256)
void k_cvt_tr(const float* __restrict__ S, __half* __restrict__ D, int R, int C)
{
    __shared__ float t[32][33];
    size_t so = (size_t)blockIdx.z * R * C;
    int c0 = blockIdx.x * 32, r0 = blockIdx.y * 32;
    int tx = threadIdx.x & 31, ty = threadIdx.x >> 5;
    #pragma unroll
    for (int i = 0; i < 4; i++)
        t[ty + i*8][tx] = S[so + (size_t)(r0 + ty + i*8) * C + c0 + tx];
    __syncthreads();
    #pragma unroll
    for (int i = 0; i < 4; i++)
        D[so + (size_t)(c0 + ty + i*8) * R + r0 + tx] = __float2half_rn(t[tx][ty + i*8]);
}

// ---------------- fp16 cp.async GEMM (3-stage pipeline) ----------------
enum { HP_DUAL = 0, HP_EXPDUAL = 1, HP_EXPDOWN = 2, HP_RESID = 3, HP_QKV = 4, HP_HALF = 5, HP_FINAL = 6 };
#define SMHP 61440

template<int MODE, int BN>
__global__ __launch_bounds__(256)
void gemm_hp(const __half* __restrict__ Aa, int lda,
             const __half* __restrict__ B1a, const __half* __restrict__ B3a,
             void* __restrict__ Cv, int ldc,
             const float* __restrict__ Da, int K)
{
    constexpr bool DUAL = (MODE == HP_DUAL || MODE == HP_EXPDUAL);
    constexpr int NT  = BN / 16;
    constexpr int BCH = BN / 64;
    extern __shared__ __half hsm[];
    __half* sA  = hsm;                       // 3 x [128][40]
    __half* sB1 = hsm + 3 * 128 * 40;        // 3 x [BN][40]
    __half* sB3 = sB1 + (DUAL ? 3 * BN * 40 : 0);

    const int tid = threadIdx.x;
    const int nb = blockIdx.x, mb = blockIdx.y, z = blockIdx.z;
    const int m0 = mb * 128, n0 = nb * BN;

    const __half* A = Aa; const __half* B1 = B1a; const __half* B3 = B3a;
    const float* wrow = nullptr; const int* ridx = nullptr;
    void* C = Cv; int ldcx = ldc;

    if (MODE == HP_EXPDUAL) {
        if (m0 >= g_cnt_pad[z]) return;
        int off = g_off_pad[z];
        ridx = g_tok_of_slot + off;
        A = g_hn_h; lda = CDIM;
        B1 = B1a + (size_t)z * FDIM * CDIM;
        B3 = B3a + (size_t)z * FDIM * CDIM;
        C = (void*)(g_hid_h + (size_t)off * FDIM); ldcx = FDIM;
    } else if (MODE == HP_EXPDOWN) {
        if (m0 >= g_cnt_pad[z]) return;
        int off = g_off_pad[z];
        A = g_hid_h + (size_t)off * FDIM; lda = FDIM;
        B1 = B1a + (size_t)z * CDIM * FDIM;
        C = (void*)(g_ctb + (size_t)off * CDIM); ldcx = CDIM;
        wrow = g_w_of_slot + off;
    }

    const int lane = tid & 31, warp = tid >> 5;
    const int wm = warp & 3, wn = warp >> 2;
    const int mw = wm * 32, nw = wn * (BN / 2);
    const int grp = lane >> 2, tig = lane & 3;

    const int KT = K >> 5;

    auto ISSUE = [&](int kt, int st) {
        if (kt < KT) {
            int k0 = kt << 5;
            #pragma unroll
            for (int t = 0; t < 2; t++) {
                int c = tid + 256 * t;
                int row = c >> 2, q = c & 3;
                int gr = (MODE == HP_EXPDUAL) ? ridx[m0 + row] : (m0 + row);
                cpa16(smem_u32(&sA[st * 128 * 40 + row * 40 + q * 8]),
                      A + (size_t)gr * lda + k0 + q * 8);
            }
            #pragma unroll
            for (int t = 0; t < BCH; t++) {
                int c = tid + 256 * t;
                int row = c >> 2, q = c & 3;
                cpa16(smem_u32(&sB1[st * BN * 40 + row * 40 + q * 8]),
                      B1 + (size_t)(n0 + row) * K + k0 + q * 8);
                if (DUAL)
                    cpa16(smem_u32(&sB3[st * BN * 40 + row * 40 + q * 8]),
                          B3 + (size_t)(n0 + row) * K + k0 + q * 8);
            }
        }
        CP_COMMIT();
    };

    float acc1[2][NT][4] = {};
    float acc3[2][DUAL ? NT : 1][4] = {};

    auto COMP = [&](int st) {
        const unsigned* uA  = (const unsigned*)(sA  + st * 128 * 40);
        const unsigned* uB1 = (const unsigned*)(sB1 + st * BN * 40);
        const unsigned* uB3 = (const unsigned*)(sB3 + st * BN * 40);
        #pragma unroll
        for (int s16 = 0; s16 < 2; s16++) {
            int ko = s16 * 8;
            unsigned bF1[NT][2], bF3[DUAL ? NT : 1][2], aF[2][4];
            #pragma unroll
            for (int j = 0; j < NT; j++) {
                int n = nw + j * 8 + grp;
                bF1[j][0] = uB1[n * 20 + ko + tig];
                bF1[j][1] = uB1[n * 20 + ko + 4 + tig];
                if (DUAL) {
                    bF3[j][0] = uB3[n * 20 + ko + tig];
                    bF3[j][1] = uB3[n * 20 + ko + 4 + tig];
                }
            }
            #pragma unroll
            for (int i = 0; i < 2; i++) {
                int m = mw + i * 16 + grp;
                aF[i][0] = uA[m * 20 + ko + tig];
                aF[i][1] = uA[(m + 8) * 20 + ko + tig];
                aF[i][2] = uA[m * 20 + ko + 4 + tig];
                aF[i][3] = uA[(m + 8) * 20 + ko + 4 + tig];
            }
            #pragma unroll
            for (int i = 0; i < 2; i++)
                #pragma unroll
                for (int j = 0; j < NT; j++) {
                    MMA_F16(acc1[i][j], aF[i], bF1[j]);
                    if (DUAL) MMA_F16(acc3[i][j], aF[i], bF3[j]);
                }
        }
    };

    ISSUE(0, 0);
    ISSUE(1, 1);
    for (int kt = 0; kt < KT; kt++) {
        int st = kt % 3;
        CP_WAIT1();
        __syncthreads();
        ISSUE(kt + 2, (kt + 2) % 3);
        COMP(st);
    }

    #pragma unroll
    for (int i = 0; i < 2; i++) {
        #pragma unroll
        for (int j = 0; j < NT; j++) {
            #pragma unroll
            for (int hh = 0; hh < 2; hh++) {
                int ml = mw + i * 16 + grp + hh * 8;
                int nl = nw + j * 8 + 2 * tig;
                float v0 = acc1[i][j][hh * 2 + 0];
                float v1 = acc1[i][j][hh * 2 + 1];
                int gm = m0 + ml, gn = n0 + nl;
                if (DUAL) {
                    v0 = v0 * siluf(acc3[i][j][hh * 2 + 0]);
                    v1 = v1 * siluf(acc3[i][j][hh * 2 + 1]);
                    *(__half2*)((__half*)C + (size_t)gm * ldcx + gn) = __floats2half2_rn(v0, v1);
                } else if (MODE == HP_EXPDOWN) {
                    float w = wrow[gm];
                    *(float2*)((float*)C + (size_t)gm * ldcx + gn) = make_float2(v0 * w, v1 * w);
                } else if (MODE == HP_RESID) {
                    float2 d = *(const float2*)(Da + (size_t)gm * ldcx + gn);
                    *(float2*)((float*)C + (size_t)gm * ldcx + gn) = make_float2(v0 + d.x, v1 + d.y);
                } else if (MODE == HP_FINAL) {
                    // out = ((acc + hb) + ctb[s0]) + ctb[s1]  (same order as separate combine)
                    int s0 = g_slot_of_tok[gm * 2];
                    int s1 = g_slot_of_tok[gm * 2 + 1];
                    float2 d  = *(const float2*)(Da + (size_t)gm * ldcx + gn);
                    float2 c0 = *(const float2*)(g_ctb + (size_t)s0 * CDIM + gn);
                    float2 c1 = *(const float2*)(g_ctb + (size_t)s1 * CDIM + gn);
                    float o0 = ((v0 + d.x) + c0.x) + c1.x;
                    float o1 = ((v1 + d.y) + c0.y) + c1.y;
                    *(float2*)((float*)C + (size_t)gm * ldcx + gn) = make_float2(o0, o1);
                } else if (MODE == HP_QKV) {
                    if (gn < 1024)
                        *(__half2*)(g_q_h + (size_t)gm * 1024 + gn) =
                            __floats2half2_rn(v0 * 0.125f, v1 * 0.125f);
                    else
                        *(__half2*)(g_kv_h + (size_t)gm * 512 + gn - 1024) =
                            __floats2half2_rn(v0, v1);
                } else {  // HP_HALF
                    *(__half2*)((__half*)C + (size_t)gm * ldcx + gn) = __floats2half2_rn(v0, v1);
                }
            }
        }
    }
}

// ---------------- fp16 flash attention (online softmax) ----------------
#define FA_BYTES 91136

__global__ __launch_bounds__(256)
void k_flash_h(const __half* __restrict__ Qg, const __half* __restrict__ KVg,
               __half* __restrict__ Og)
{
    extern __shared__ __half fh[];
    __half* sQ  = fh;            // [128][72]
    __half* sK  = fh + 9216;     // [128][72]
    __half* sVt = fh + 18432;    // [64][136]  V transposed [d][s]
    __half* sP  = fh + 27136;    // [128][136]
    float* sRM = (float*)(fh + 44544);
    float* sRS = sRM + 256;
    const unsigned* uQ  = (const unsigned*)sQ;
    const unsigned* uK  = (const unsigned*)sK;
    const unsigned* uVt = (const unsigned*)sVt;
    unsigned* uP = (unsigned*)sP;

    const int qt = blockIdx.x, bh = blockIdx.y;
    const int b = bh >> 4, hh = bh & 15;
    const int tid = threadIdx.x, warp = tid >> 5, lane = tid & 31;
    const int wm = warp & 3, wn = warp >> 2;
    const int grp = lane >> 2, tig = lane & 3;
    const float NEG = -1e30f;

    const __half* Qb = Qg + (size_t)(b*1024 + qt*128) * 1024 + hh*64;
    #pragma unroll
    for (int t = 0; t < 4; t++) {
        int idx = tid + t*256;
        int r = idx >> 3, c = idx & 7;
        *(uint4*)&sQ[r*72 + c*8] = *(const uint4*)(Qb + (size_t)r*1024 + c*8);
    }

    float m_i[2][2] = {{NEG,NEG},{NEG,NEG}};
    float l_i[2][2] = {{0.f,0.f},{0.f,0.f}};
    float oacc[2][4][4] = {};

    for (int kt = 0; kt <= qt; kt++) {
        __syncthreads();
        const __half* KVb = KVg + (size_t)(b*1024 + kt*128) * 128;
        #pragma unroll
        for (int t = 0; t < 4; t++) {
            int idx = tid + t*256;
            int r = idx >> 3, c = idx & 7;
            *(uint4*)&sK[r*72 + c*8] = *(const uint4*)(KVb + (size_t)r*128 + c*8);
            uint4 vv = *(const uint4*)(KVb + (size_t)r*128 + 64 + c*8);
            __half tmp[8];
            memcpy(tmp, &vv, 16);
            #pragma unroll
            for (int i = 0; i < 8; i++)
                sVt[(c*8 + i)*136 + r] = tmp[i];
        }
        __syncthreads();

        float sacc[2][8][4] = {};
        #pragma unroll
        for (int ks = 0; ks < 4; ks++) {
            int ko = ks * 8;
            unsigned aF[2][4], bF[8][2];
            #pragma unroll
            for (int j = 0; j < 8; j++) {
                int n = wn*64 + j*8 + grp;
                bF[j][0] = uK[n*36 + ko + tig];
                bF[j][1] = uK[n*36 + ko + 4 + tig];
            }
            #pragma unroll
            for (int i = 0; i < 2; i++) {
                int m = wm*32 + i*16 + grp;
                aF[i][0] = uQ[m*36 + ko + tig];
                aF[i][1] = uQ[(m+8)*36 + ko + tig];
                aF[i][2] = uQ[m*36 + ko + 4 + tig];
                aF[i][3] = uQ[(m+8)*36 + ko + 4 + tig];
            }
            #pragma unroll
            for (int i = 0; i < 2; i++)
                #pragma unroll
                for (int j = 0; j < 8; j++)
                    MMA_F16(sacc[i][j], aF[i], bF[j]);
        }

        if (kt == qt) {
            #pragma unroll
            for (int i = 0; i < 2; i++)
                #pragma unroll
                for (int h2 = 0; h2 < 2; h2++) {
                    int row = wm*32 + i*16 + grp + h2*8;
                    #pragma unroll
                    for (int j = 0; j < 8; j++) {
                        int col = wn*64 + j*8 + 2*tig;
                        if (col   > row) sacc[i][j][h2*2]   = NEG;
                        if (col+1 > row) sacc[i][j][h2*2+1] = NEG;
                    }
                }
        }

        #pragma unroll
        for (int i = 0; i < 2; i++)
            #pragma unroll
            for (int h2 = 0; h2 < 2; h2++) {
                float v = NEG;
                #pragma unroll
                for (int j = 0; j < 8; j++)
                    v = fmaxf(v, fmaxf(sacc[i][j][h2*2], sacc[i][j][h2*2+1]));
                v = fmaxf(v, __shfl_xor_sync(0xffffffffu, v, 1));
                v = fmaxf(v, __shfl_xor_sync(0xffffffffu, v, 2));
                if (tig == 0) sRM[wn*128 + wm*32 + i*16 + grp + h2*8] = v;
            }
        __syncthreads();

        #pragma unroll
        for (int i = 0; i < 2; i++)
            #pragma unroll
            for (int h2 = 0; h2 < 2; h2++) {
                int row = wm*32 + i*16 + grp + h2*8;
                float mnew = fmaxf(m_i[i][h2], fmaxf(sRM[row], sRM[128+row]));
                float fac = __expf(m_i[i][h2] - mnew);
                m_i[i][h2] = mnew;
                l_i[i][h2] *= fac;
                #pragma unroll
                for (int j = 0; j < 4; j++) {
                    oacc[i][j][h2*2]   *= fac;
                    oacc[i][j][h2*2+1] *= fac;
                }
                float rs = 0.0f;
                #pragma unroll
                for (int j = 0; j < 8; j++) {
                    float p0 = __expf(sacc[i][j][h2*2]   - mnew);
                    float p1 = __expf(sacc[i][j][h2*2+1] - mnew);
                    rs += p0 + p1;
                    int cu = wn*32 + j*4 + tig;
                    uP[row*68 + cu] = h2_as_u32(__floats2half2_rn(p0, p1));
                }
                rs += __shfl_xor_sync(0xffffffffu, rs, 1);
                rs += __shfl_xor_sync(0xffffffffu, rs, 2);
                if (tig == 0) sRS[wn*128 + row] = rs;
            }
        __syncthreads();
        #pragma unroll
        for (int i = 0; i < 2; i++)
            #pragma unroll
            for (int h2 = 0; h2 < 2; h2++) {
                int row = wm*32 + i*16 + grp + h2*8;
                l_i[i][h2] += sRS[row] + sRS[128 + row];
            }

        #pragma unroll
        for (int ks = 0; ks < 8; ks++) {
            int ko = ks * 8;
            unsigned aF[2][4], bF[4][2];
            #pragma unroll
            for (int j = 0; j < 4; j++) {
                int n = wn*32 + j*8 + grp;
                bF[j][0] = uVt[n*68 + ko + tig];
                bF[j][1] = uVt[n*68 + ko + 4 + tig];
            }
            #pragma unroll
            for (int i = 0; i < 2; i++) {
                int m = wm*32 + i*16 + grp;
                aF[i][0] = uP[m*68 + ko + tig];
                aF[i][1] = uP[(m+8)*68 + ko + tig];
                aF[i][2] = uP[m*68 + ko + 4 + tig];
                aF[i][3] = uP[(m+8)*68 + ko + 4 + tig];
            }
            #pragma unroll
            for (int i = 0; i < 2; i++)
                #pragma unroll
                for (int j = 0; j < 4; j++)
                    MMA_F16(oacc[i][j], aF[i], bF[j]);
        }
    }

    __half* Ob = Og + (size_t)(b*1024 + qt*128) * 1024 + hh*64;
    #pragma unroll
    for (int i = 0; i < 2; i++)
        #pragma unroll
        for (int h2 = 0; h2 < 2; h2++) {
            int row = wm*32 + i*16 + grp + h2*8;
            float inv = 1.0f / l_i[i][h2];
            #pragma unroll
            for (int j = 0; j < 4; j++) {
                int col = wn*32 + j*8 + 2*tig;
                *(__half2*)(Ob + (size_t)row*1024 + col) =
                    __floats2half2_rn(oacc[i][j][h2*2]*inv, oacc[i][j][h2*2+1]*inv);
            }
        }
}

// ---------------- elementwise / small kernels ----------------
__global__ __launch_bounds__(256)
void k_rmsnorm(const float* __restrict__ X, const float* __restrict__ G,
               float* __restrict__ Of, __half* __restrict__ Oh)
{
    int n = blockIdx.x;
    const float4* x4 = (const float4*)(X + (size_t)n * CDIM);
    const float4* g4 = (const float4*)G;
    float4 v = x4[threadIdx.x];
    float ss = v.x*v.x + v.y*v.y + v.z*v.z + v.w*v.w;
    float tot = block_reduce_sum256(ss);
    float r = 1.0f / sqrtf(tot * (1.0f / CDIM) + 1e-6f);
    float4 g = g4[threadIdx.x];
    float4 full = make_float4(v.x*r*g.x, v.y*r*g.y, v.z*r*g.z, v.w*r*g.w);
    if (Of) ((float4*)(Of + (size_t)n * CDIM))[threadIdx.x] = full;
    if (Oh) {
        *(__half2*)(Oh + (size_t)n * CDIM + threadIdx.x * 4)     = __floats2half2_rn(full.x, full.y);
        *(__half2*)(Oh + (size_t)n * CDIM + threadIdx.x * 4 + 2) = __floats2half2_rn(full.z, full.w);
    }
}

__global__ __launch_bounds__(128)
void k_router(const float* __restrict__ HN, const float* __restrict__ WR,
              const float* __restrict__ RB)
{
    int n = blockIdx.x * 4 + (threadIdx.x >> 5);
    int lane = threadIdx.x & 31;
    const float* x = HN + (size_t)n * CDIM;
    float p[NEXP] = {};
    for (int c = lane; c < CDIM; c += 32) {
        float xv = x[c];
        #pragma unroll
        for (int e = 0; e < NEXP; e++) p[e] += xv * WR[c * NEXP + e];
    }
    #pragma unroll
    for (int e = 0; e < NEXP; e++) {
        #pragma unroll
        for (int o = 16; o; o >>= 1)
            p[e] += __shfl_xor_sync(0xffffffffu, p[e], o);
    }
    if (lane == 0) {
        float logit[NEXP], biased[NEXP];
        #pragma unroll
        for (int e = 0; e < NEXP; e++) {
            logit[e]  = p[e] * 0.03125f;
            biased[e] = logit[e] + RB[e];
        }
        int i0 = 0;
        #pragma unroll
        for (int e = 1; e < NEXP; e++) if (biased[e] > biased[i0]) i0 = e;
        int i1 = -1;
        #pragma unroll
        for (int e = 0; e < NEXP; e++) {
            if (e == i0) continue;
            if (i1 < 0 || biased[e] > biased[i1]) i1 = e;
        }
        float m  = fmaxf(logit[i0], logit[i1]);
        float e0 = expf(logit[i0] - m), e1 = expf(logit[i1] - m);
        float inv = 1.0f / (e0 + e1);
        g_top [n*2]     = i0; g_top [n*2 + 1] = i1;
        g_topw[n*2]     = e0 * inv;
        g_topw[n*2 + 1] = e1 * inv;
    }
}

__global__ __launch_bounds__(256)
void k_place()
{
    __shared__ int cnt[NEXP], offp[NEXP], cntp[NEXP], cur[NEXP];
    int tid = threadIdx.x;
    if (tid < NEXP) cnt[tid] = 0;
    __syncthreads();
    for (int i = tid; i < NTOK * 2; i += 256) atomicAdd(&cnt[g_top[i]], 1);
    __syncthreads();
    if (tid == 0) {
        int o = 0;
        for (int e = 0; e < NEXP; e++) {
            offp[e] = o;
            cntp[e] = ((cnt[e] + 127) >> 7) << 7;
            cur[e]  = o;
            g_off_pad[e] = o;
            g_cnt_pad[e] = cntp[e];
            o += cntp[e];
        }
    }
    __syncthreads();
    for (int i = tid; i < NTOK * 2; i += 256) {
        int e = g_top[i];
        int s = atomicAdd(&cur[e], 1);
        g_tok_of_slot[s] = i >> 1;
        g_w_of_slot[s]   = g_topw[i];
        g_slot_of_tok[i] = s;
    }
    __syncthreads();
    for (int e = 0; e < NEXP; e++) {
        int start = offp[e] + cnt[e];
        int end   = offp[e] + cntp[e];
        for (int i = start + tid; i < end; i += 256) {
            g_tok_of_slot[i] = 0;
            g_w_of_slot[i]   = 0.0f;
        }
    }
}

// ---------------- launch ----------------
extern "C" void kernel_launch(void* const* d_in, const int* in_sizes, int n_in,
                              void* d_out, int out_size)
{
    const float* x    = (const float*)d_in[0];
    const float* ga   = (const float*)d_in[1];
    const float* wq   = (const float*)d_in[2];
    const float* wkvd = (const float*)d_in[3];
    const float* wku  = (const float*)d_in[4];
    const float* wvu  = (const float*)d_in[5];
    const float* wo   = (const float*)d_in[6];
    const float* gm   = (const float*)d_in[7];
    const float* wr   = (const float*)d_in[8];
    const float* rb   = (const float*)d_in[9];
    const float* ew1  = (const float*)d_in[10];
    const float* ew2  = (const float*)d_in[11];
    const float* ew3  = (const float*)d_in[12];
    const float* sw1  = (const float*)d_in[13];
    const float* sw2  = (const float*)d_in[14];
    const float* sw3  = (const float*)d_in[15];
    float* out = (float*)d_out;

    float *hb, *hnf;
    __half *xn_h, *q_h, *kv_h, *kvo_h, *att_h, *hn_h, *shid_h;
    __half *wqkv_h, *wkv_h, *wo_h, *sw1_h, *sw3_h, *sw2_h, *ew1_h, *ew2_h, *ew3_h;
    cudaGetSymbolAddress((void**)&hb,   g_h);
    cudaGetSymbolAddress((void**)&hnf,  g_hnf);
    cudaGetSymbolAddress((void**)&xn_h,  g_xn_h);
    cudaGetSymbolAddress((void**)&q_h,   g_q_h);
    cudaGetSymbolAddress((void**)&kv_h,  g_kv_h);
    cudaGetSymbolAddress((void**)&kvo_h, g_kvo_h);
    cudaGetSymbolAddress((void**)&att_h, g_att_h);
    cudaGetSymbolAddress((void**)&hn_h,  g_hn_h);
    cudaGetSymbolAddress((void**)&shid_h, g_shid_h);
    cudaGetSymbolAddress((void**)&wqkv_h, g_wqkv_h);
    cudaGetSymbolAddress((void**)&wkv_h,  g_wkv_h);
    cudaGetSymbolAddress((void**)&wo_h,   g_wo_h);
    cudaGetSymbolAddress((void**)&sw1_h,  g_sw1_h);
    cudaGetSymbolAddress((void**)&sw3_h,  g_sw3_h);
    cudaGetSymbolAddress((void**)&sw2_h,  g_sw2_h);
    cudaGetSymbolAddress((void**)&ew1_h,  g_ew1_h);
    cudaGetSymbolAddress((void**)&ew2_h,  g_ew2_h);
    cudaGetSymbolAddress((void**)&ew3_h,  g_ew3_h);

    cudaFuncSetAttribute(k_flash_h, cudaFuncAttributeMaxDynamicSharedMemorySize, FA_BYTES);
    cudaFuncSetAttribute(gemm_hp<HP_DUAL,64>,     cudaFuncAttributeMaxDynamicSharedMemorySize, SMHP);
    cudaFuncSetAttribute(gemm_hp<HP_EXPDUAL,64>,  cudaFuncAttributeMaxDynamicSharedMemorySize, SMHP);
    cudaFuncSetAttribute(gemm_hp<HP_EXPDOWN,128>, cudaFuncAttributeMaxDynamicSharedMemorySize, SMHP);
    cudaFuncSetAttribute(gemm_hp<HP_RESID,128>,   cudaFuncAttributeMaxDynamicSharedMemorySize, SMHP);
    cudaFuncSetAttribute(gemm_hp<HP_QKV,128>,     cudaFuncAttributeMaxDynamicSharedMemorySize, SMHP);
    cudaFuncSetAttribute(gemm_hp<HP_HALF,128>,    cudaFuncAttributeMaxDynamicSharedMemorySize, SMHP);
    cudaFuncSetAttribute(gemm_hp<HP_FINAL,128>,   cudaFuncAttributeMaxDynamicSharedMemorySize, SMHP);

    // lazily-created side stream + events (host objects only; same work every call)
    static cudaStream_t s1 = nullptr;
    static cudaEvent_t ev_fork = nullptr, ev_join = nullptr;
    if (!s1) {
        cudaStreamCreateWithFlags(&s1, cudaStreamNonBlocking);
        cudaEventCreateWithFlags(&ev_fork, cudaEventDisableTiming);
        cudaEventCreateWithFlags(&ev_join, cudaEventDisableTiming);
    }

    // ---- fork: MoE + wo weight prep on side stream, overlapped with attention ----
    cudaEventRecord(ev_fork, 0);
    cudaStreamWaitEvent(s1, ev_fork, 0);
    k_cvt_tr<<<dim3(32, 32), 256, 0, s1>>>(wo, wo_h, 1024, 1024);
    k_cvt_tr<<<dim3(32, 32, NEXP), 256, 0, s1>>>(ew1, ew1_h, CDIM, FDIM);
    k_cvt_tr<<<dim3(32, 32, NEXP), 256, 0, s1>>>(ew3, ew3_h, CDIM, FDIM);
    k_cvt_tr<<<dim3(32, 32, NEXP), 256, 0, s1>>>(ew2, ew2_h, FDIM, CDIM);
    k_cvt_tr<<<dim3(64, 32), 256, 0, s1>>>(sw1, sw1_h, CDIM, FSH);
    k_cvt_tr<<<dim3(64, 32), 256, 0, s1>>>(sw3, sw3_h, CDIM, FSH);
    k_cvt_tr<<<dim3(32, 64), 256, 0, s1>>>(sw2, sw2_h, FSH, CDIM);
    cudaEventRecord(ev_join, s1);

    // ---- main stream: attention-critical weight prep ----
    k_cvt_tr<<<dim3(32, 32), 256>>>(wq,   wqkv_h,             1024, 1024);
    k_cvt_tr<<<dim3(16, 32), 256>>>(wkvd, wqkv_h + 1024*1024, 1024, 512);
    k_cvt_tr<<<dim3(2, 16), 256>>>(wku,  wkv_h,              512,  64);
    k_cvt_tr<<<dim3(2, 16), 256>>>(wvu,  wkv_h + 64*512,     512,  64);

    // ---- attention (fp16) ----
    k_rmsnorm<<<NTOK, 256>>>(x, ga, nullptr, xn_h);
    gemm_hp<HP_QKV,128><<<dim3(12, 32), 256, SMHP>>>(xn_h, 1024, wqkv_h, nullptr, nullptr, 0, nullptr, 1024);
    gemm_hp<HP_HALF,128><<<dim3(1, 32), 256, SMHP>>>(kv_h, 512, wkv_h, nullptr, kvo_h, 128, nullptr, 512);
    k_flash_h<<<dim3(8, 64), 256, FA_BYTES>>>(q_h, kvo_h, att_h);

    // ---- join: side-stream weight prep must be done before wo / MoE weights used ----
    cudaStreamWaitEvent(0, ev_join, 0);
    gemm_hp<HP_RESID,128><<<dim3(8, 32), 256, SMHP>>>(att_h, 1024, wo_h, nullptr, hb, 1024, x, 1024);

    // ---- MoE (fp16) ----
    k_rmsnorm<<<NTOK, 256>>>(hb, gm, hnf, hn_h);
    k_router<<<NTOK/4, 128>>>(hnf, wr, rb);
    k_place<<<1, 256>>>();
    gemm_hp<HP_EXPDUAL,64><<<dim3(16, 72, NEXP), 256, SMHP>>>(nullptr, 0, ew1_h, ew3_h, nullptr, 0, nullptr, 1024);
    gemm_hp<HP_EXPDOWN,128><<<dim3(8, 72, NEXP), 256, SMHP>>>(nullptr, 0, ew2_h, nullptr, nullptr, 0, nullptr, 1024);
    gemm_hp<HP_DUAL,64><<<dim3(32, 32), 256, SMHP>>>(hn_h, 1024, sw1_h, sw3_h, shid_h, 2048, nullptr, 1024);
    gemm_hp<HP_FINAL,128><<<dim3(8, 32), 256, SMHP>>>(shid_h, 2048, sw2_h, nullptr, out, 1024, hb, 2048);
}

// round 17
// speedup vs baseline: 1.0805x; 1.0136x over previous
#include <cuda_runtime.h>
#include <cuda_fp16.h>
#include <math.h>
#include <stdint.h>
#include <string.h>

// ---------------- problem dims ----------------
#define NTOK 4096
#define CDIM 1024
#define HD 64
#define LAT 512
#define NEXP 8
#define FDIM 1024
#define FSH 2048
#define MAXSLOT 9216

// ---------------- scratch ----------------
__device__ __half g_xn_h [NTOK*CDIM];
__device__ __half g_q_h  [NTOK*CDIM];      // pre-scaled by 0.125
__device__ __half g_kv_h [NTOK*LAT];
__device__ __half g_kvo_h[NTOK*128];       // K|V interleaved per row
__device__ __half g_att_h[NTOK*CDIM];
__device__ float  g_h    [NTOK*CDIM];
__device__ float  g_hnf  [NTOK*CDIM];      // full fp32 (router only)
__device__ __half g_hn_h [NTOK*CDIM];      // half (MoE GEMM operand)
__device__ int    g_top[NTOK*2];
__device__ float  g_topw[NTOK*2];
__device__ int    g_tok_of_slot[MAXSLOT];
__device__ float  g_w_of_slot[MAXSLOT];
__device__ int    g_slot_of_tok[NTOK*2];
__device__ int    g_off_pad[NEXP];
__device__ int    g_cnt_pad[NEXP];
__device__ __half g_hid_h [MAXSLOT*FDIM];
__device__ float  g_ctb   [MAXSLOT*CDIM];
__device__ __half g_shid_h[NTOK*FSH];

// half weights, transposed to [N][K]
__device__ __half g_wqkv_h[1536*CDIM];
__device__ __half g_wkv_h [128*LAT];
__device__ __half g_wo_h  [CDIM*CDIM];
__device__ __half g_sw1_h[FSH*CDIM];
__device__ __half g_sw3_h[FSH*CDIM];
__device__ __half g_sw2_h[CDIM*FSH];
__device__ __half g_ew1_h[NEXP*FDIM*CDIM];
__device__ __half g_ew3_h[NEXP*FDIM*CDIM];
__device__ __half g_ew2_h[NEXP*CDIM*FDIM];

// ---------------- helpers ----------------
__device__ __forceinline__ float siluf(float x) { return x / (1.0f + expf(-x)); }

__device__ __forceinline__ unsigned h2_as_u32(__half2 h) {
    unsigned u;
    memcpy(&u, &h, 4);
    return u;
}

__device__ __forceinline__ uint32_t smem_u32(const void* p) {
    uint32_t a;
    asm("{ .reg .u64 t; cvta.to.shared.u64 t, %1; cvt.u32.u64 %0, t; }" : "=r"(a) : "l"(p));
    return a;
}
__device__ __forceinline__ void cpa16(uint32_t saddr, const void* g) {
    asm volatile("cp.async.cg.shared.global [%0], [%1], 16;" :: "r"(saddr), "l"(g));
}
#define CP_COMMIT() asm volatile("cp.async.commit_group;" ::: "memory")
#define CP_WAIT1()  asm volatile("cp.async.wait_group 1;" ::: "memory")

#define MMA_F16(d, a, b) asm volatile( \
  "mma.sync.aligned.m16n8k16.row.col.f32.f16.f16.f32 " \
  "{%0,%1,%2,%3}, {%4,%5,%6,%7}, {%8,%9}, {%0,%1,%2,%3};" \
  : "+f"(d[0]), "+f"(d[1]), "+f"(d[2]), "+f"(d[3]) \
  : "r"(a[0]), "r"(a[1]), "r"(a[2]), "r"(a[3]), "r"(b[0]), "r"(b[1]))

__device__ __forceinline__ float block_reduce_sum256(float v) {
    __shared__ float sm[8];
    __syncthreads();
    int lane = threadIdx.x & 31, w = threadIdx.x >> 5;
    #pragma unroll
    for (int o = 16; o; o >>= 1) v += __shfl_xor_sync(0xffffffffu, v, o);
    if (lane == 0) sm[w] = v;
    __syncthreads();
    float r = (threadIdx.x < 8) ? sm[threadIdx.x] : 0.0f;
    if (w == 0) {
        #pragma unroll
        for (int o = 4; o; o >>= 1) r += __shfl_xor_sync(0xffffffffu, r, o);
        if (lane == 0) sm[0] = r;
    }
    __syncthreads();
    return sm[0];
}

// ---------------- weight prep: src [R][C] fp32 (batched by z) -> dst [C][R] half --
__global__ __launch_bounds__(256)
void k_cvt_tr(const float* __restrict__ S, __half* __restrict__ D, int R, int C)
{
    __shared__ float t[32][33];
    size_t so = (size_t)blockIdx.z * R * C;
    int c0 = blockIdx.x * 32, r0 = blockIdx.y * 32;
    int tx = threadIdx.x & 31, ty = threadIdx.x >> 5;
    #pragma unroll
    for (int i = 0; i < 4; i++)
        t[ty + i*8][tx] = S[so + (size_t)(r0 + ty + i*8) * C + c0 + tx];
    __syncthreads();
    #pragma unroll
    for (int i = 0; i < 4; i++)
        D[so + (size_t)(c0 + ty + i*8) * R + r0 + tx] = __float2half_rn(t[tx][ty + i*8]);
}

// ---------------- fp16 cp.async GEMM (3-stage pipeline) ----------------
enum { HP_DUAL = 0, HP_EXPDUAL = 1, HP_EXPDOWN = 2, HP_RESID = 3, HP_QKV = 4, HP_HALF = 5, HP_FINAL = 6 };
#define SMHP 61440

template<int MODE, int BN>
__global__ __launch_bounds__(256)
void gemm_hp(const __half* __restrict__ Aa, int lda,
             const __half* __restrict__ B1a, const __half* __restrict__ B3a,
             void* __restrict__ Cv, int ldc,
             const float* __restrict__ Da, int K)
{
    constexpr bool DUAL = (MODE == HP_DUAL || MODE == HP_EXPDUAL);
    constexpr int NT  = BN / 16;
    constexpr int BCH = BN / 64;
    extern __shared__ __half hsm[];
    __half* sA  = hsm;                       // 3 x [128][40]
    __half* sB1 = hsm + 3 * 128 * 40;        // 3 x [BN][40]
    __half* sB3 = sB1 + (DUAL ? 3 * BN * 40 : 0);

    const int tid = threadIdx.x;
    const int nb = blockIdx.x, mb = blockIdx.y, z = blockIdx.z;
    const int m0 = mb * 128, n0 = nb * BN;

    const __half* A = Aa; const __half* B1 = B1a; const __half* B3 = B3a;
    const float* wrow = nullptr; const int* ridx = nullptr;
    void* C = Cv; int ldcx = ldc;

    if (MODE == HP_EXPDUAL) {
        if (m0 >= g_cnt_pad[z]) return;
        int off = g_off_pad[z];
        ridx = g_tok_of_slot + off;
        A = g_hn_h; lda = CDIM;
        B1 = B1a + (size_t)z * FDIM * CDIM;
        B3 = B3a + (size_t)z * FDIM * CDIM;
        C = (void*)(g_hid_h + (size_t)off * FDIM); ldcx = FDIM;
    } else if (MODE == HP_EXPDOWN) {
        if (m0 >= g_cnt_pad[z]) return;
        int off = g_off_pad[z];
        A = g_hid_h + (size_t)off * FDIM; lda = FDIM;
        B1 = B1a + (size_t)z * CDIM * FDIM;
        C = (void*)(g_ctb + (size_t)off * CDIM); ldcx = CDIM;
        wrow = g_w_of_slot + off;
    }

    const int lane = tid & 31, warp = tid >> 5;
    const int wm = warp & 3, wn = warp >> 2;
    const int mw = wm * 32, nw = wn * (BN / 2);
    const int grp = lane >> 2, tig = lane & 3;

    const int KT = K >> 5;

    auto ISSUE = [&](int kt, int st) {
        if (kt < KT) {
            int k0 = kt << 5;
            #pragma unroll
            for (int t = 0; t < 2; t++) {
                int c = tid + 256 * t;
                int row = c >> 2, q = c & 3;
                int gr = (MODE == HP_EXPDUAL) ? ridx[m0 + row] : (m0 + row);
                cpa16(smem_u32(&sA[st * 128 * 40 + row * 40 + q * 8]),
                      A + (size_t)gr * lda + k0 + q * 8);
            }
            #pragma unroll
            for (int t = 0; t < BCH; t++) {
                int c = tid + 256 * t;
                int row = c >> 2, q = c & 3;
                cpa16(smem_u32(&sB1[st * BN * 40 + row * 40 + q * 8]),
                      B1 + (size_t)(n0 + row) * K + k0 + q * 8);
                if (DUAL)
                    cpa16(smem_u32(&sB3[st * BN * 40 + row * 40 + q * 8]),
                          B3 + (size_t)(n0 + row) * K + k0 + q * 8);
            }
        }
        CP_COMMIT();
    };

    float acc1[2][NT][4] = {};
    float acc3[2][DUAL ? NT : 1][4] = {};

    auto COMP = [&](int st) {
        const unsigned* uA  = (const unsigned*)(sA  + st * 128 * 40);
        const unsigned* uB1 = (const unsigned*)(sB1 + st * BN * 40);
        const unsigned* uB3 = (const unsigned*)(sB3 + st * BN * 40);
        #pragma unroll
        for (int s16 = 0; s16 < 2; s16++) {
            int ko = s16 * 8;
            unsigned bF1[NT][2], bF3[DUAL ? NT : 1][2], aF[2][4];
            #pragma unroll
            for (int j = 0; j < NT; j++) {
                int n = nw + j * 8 + grp;
                bF1[j][0] = uB1[n * 20 + ko + tig];
                bF1[j][1] = uB1[n * 20 + ko + 4 + tig];
                if (DUAL) {
                    bF3[j][0] = uB3[n * 20 + ko + tig];
                    bF3[j][1] = uB3[n * 20 + ko + 4 + tig];
                }
            }
            #pragma unroll
            for (int i = 0; i < 2; i++) {
                int m = mw + i * 16 + grp;
                aF[i][0] = uA[m * 20 + ko + tig];
                aF[i][1] = uA[(m + 8) * 20 + ko + tig];
                aF[i][2] = uA[m * 20 + ko + 4 + tig];
                aF[i][3] = uA[(m + 8) * 20 + ko + 4 + tig];
            }
            #pragma unroll
            for (int i = 0; i < 2; i++)
                #pragma unroll
                for (int j = 0; j < NT; j++) {
                    MMA_F16(acc1[i][j], aF[i], bF1[j]);
                    if (DUAL) MMA_F16(acc3[i][j], aF[i], bF3[j]);
                }
        }
    };

    ISSUE(0, 0);
    ISSUE(1, 1);
    for (int kt = 0; kt < KT; kt++) {
        int st = kt % 3;
        CP_WAIT1();
        __syncthreads();
        ISSUE(kt + 2, (kt + 2) % 3);
        COMP(st);
    }

    #pragma unroll
    for (int i = 0; i < 2; i++) {
        #pragma unroll
        for (int j = 0; j < NT; j++) {
            #pragma unroll
            for (int hh = 0; hh < 2; hh++) {
                int ml = mw + i * 16 + grp + hh * 8;
                int nl = nw + j * 8 + 2 * tig;
                float v0 = acc1[i][j][hh * 2 + 0];
                float v1 = acc1[i][j][hh * 2 + 1];
                int gm = m0 + ml, gn = n0 + nl;
                if (DUAL) {
                    v0 = v0 * siluf(acc3[i][j][hh * 2 + 0]);
                    v1 = v1 * siluf(acc3[i][j][hh * 2 + 1]);
                    *(__half2*)((__half*)C + (size_t)gm * ldcx + gn) = __floats2half2_rn(v0, v1);
                } else if (MODE == HP_EXPDOWN) {
                    float w = wrow[gm];
                    *(float2*)((float*)C + (size_t)gm * ldcx + gn) = make_float2(v0 * w, v1 * w);
                } else if (MODE == HP_RESID) {
                    float2 d = *(const float2*)(Da + (size_t)gm * ldcx + gn);
                    *(float2*)((float*)C + (size_t)gm * ldcx + gn) = make_float2(v0 + d.x, v1 + d.y);
                } else if (MODE == HP_FINAL) {
                    int s0 = g_slot_of_tok[gm * 2];
                    int s1 = g_slot_of_tok[gm * 2 + 1];
                    float2 d  = *(const float2*)(Da + (size_t)gm * ldcx + gn);
                    float2 c0 = *(const float2*)(g_ctb + (size_t)s0 * CDIM + gn);
                    float2 c1 = *(const float2*)(g_ctb + (size_t)s1 * CDIM + gn);
                    float o0 = ((v0 + d.x) + c0.x) + c1.x;
                    float o1 = ((v1 + d.y) + c0.y) + c1.y;
                    *(float2*)((float*)C + (size_t)gm * ldcx + gn) = make_float2(o0, o1);
                } else if (MODE == HP_QKV) {
                    if (gn < 1024)
                        *(__half2*)(g_q_h + (size_t)gm * 1024 + gn) =
                            __floats2half2_rn(v0 * 0.125f, v1 * 0.125f);
                    else
                        *(__half2*)(g_kv_h + (size_t)gm * 512 + gn - 1024) =
                            __floats2half2_rn(v0, v1);
                } else {  // HP_HALF
                    *(__half2*)((__half*)C + (size_t)gm * ldcx + gn) = __floats2half2_rn(v0, v1);
                }
            }
        }
    }
}

// ---------------- fp16 flash attention (online softmax, balanced pairs) --------
// grid (4, 64): CTA px handles qt = px and qt = 7-px -> 9 KV-tile iters each.
#define FA_BYTES 91136

__global__ __launch_bounds__(256)
void k_flash_h(const __half* __restrict__ Qg, const __half* __restrict__ KVg,
               __half* __restrict__ Og)
{
    extern __shared__ __half fh[];
    __half* sQ  = fh;            // [128][72]
    __half* sK  = fh + 9216;     // [128][72]
    __half* sVt = fh + 18432;    // [64][136]  V transposed [d][s]
    __half* sP  = fh + 27136;    // [128][136]
    float* sRM = (float*)(fh + 44544);
    float* sRS = sRM + 256;
    const unsigned* uQ  = (const unsigned*)sQ;
    const unsigned* uK  = (const unsigned*)sK;
    const unsigned* uVt = (const unsigned*)sVt;
    unsigned* uP = (unsigned*)sP;

    const int px = blockIdx.x, bh = blockIdx.y;
    const int b = bh >> 4, hh = bh & 15;
    const int tid = threadIdx.x, warp = tid >> 5, lane = tid & 31;
    const int wm = warp & 3, wn = warp >> 2;
    const int grp = lane >> 2, tig = lane & 3;
    const float NEG = -1e30f;

    #pragma unroll
    for (int sel = 0; sel < 2; sel++) {
        const int qt = sel ? (7 - px) : px;
        __syncthreads();   // protect smem from previous q-tile's consumers

        const __half* Qb = Qg + (size_t)(b*1024 + qt*128) * 1024 + hh*64;
        #pragma unroll
        for (int t = 0; t < 4; t++) {
            int idx = tid + t*256;
            int r = idx >> 3, c = idx & 7;
            *(uint4*)&sQ[r*72 + c*8] = *(const uint4*)(Qb + (size_t)r*1024 + c*8);
        }

        float m_i[2][2] = {{NEG,NEG},{NEG,NEG}};
        float l_i[2][2] = {{0.f,0.f},{0.f,0.f}};
        float oacc[2][4][4] = {};

        for (int kt = 0; kt <= qt; kt++) {
            __syncthreads();
            const __half* KVb = KVg + (size_t)(b*1024 + kt*128) * 128;
            #pragma unroll
            for (int t = 0; t < 4; t++) {
                int idx = tid + t*256;
                int r = idx >> 3, c = idx & 7;
                *(uint4*)&sK[r*72 + c*8] = *(const uint4*)(KVb + (size_t)r*128 + c*8);
                uint4 vv = *(const uint4*)(KVb + (size_t)r*128 + 64 + c*8);
                __half tmp[8];
                memcpy(tmp, &vv, 16);
                #pragma unroll
                for (int i = 0; i < 8; i++)
                    sVt[(c*8 + i)*136 + r] = tmp[i];
            }
            __syncthreads();

            float sacc[2][8][4] = {};
            #pragma unroll
            for (int ks = 0; ks < 4; ks++) {
                int ko = ks * 8;
                unsigned aF[2][4], bF[8][2];
                #pragma unroll
                for (int j = 0; j < 8; j++) {
                    int n = wn*64 + j*8 + grp;
                    bF[j][0] = uK[n*36 + ko + tig];
                    bF[j][1] = uK[n*36 + ko + 4 + tig];
                }
                #pragma unroll
                for (int i = 0; i < 2; i++) {
                    int m = wm*32 + i*16 + grp;
                    aF[i][0] = uQ[m*36 + ko + tig];
                    aF[i][1] = uQ[(m+8)*36 + ko + tig];
                    aF[i][2] = uQ[m*36 + ko + 4 + tig];
                    aF[i][3] = uQ[(m+8)*36 + ko + 4 + tig];
                }
                #pragma unroll
                for (int i = 0; i < 2; i++)
                    #pragma unroll
                    for (int j = 0; j < 8; j++)
                        MMA_F16(sacc[i][j], aF[i], bF[j]);
            }

            if (kt == qt) {
                #pragma unroll
                for (int i = 0; i < 2; i++)
                    #pragma unroll
                    for (int h2 = 0; h2 < 2; h2++) {
                        int row = wm*32 + i*16 + grp + h2*8;
                        #pragma unroll
                        for (int j = 0; j < 8; j++) {
                            int col = wn*64 + j*8 + 2*tig;
                            if (col   > row) sacc[i][j][h2*2]   = NEG;
                            if (col+1 > row) sacc[i][j][h2*2+1] = NEG;
                        }
                    }
            }

            #pragma unroll
            for (int i = 0; i < 2; i++)
                #pragma unroll
                for (int h2 = 0; h2 < 2; h2++) {
                    float v = NEG;
                    #pragma unroll
                    for (int j = 0; j < 8; j++)
                        v = fmaxf(v, fmaxf(sacc[i][j][h2*2], sacc[i][j][h2*2+1]));
                    v = fmaxf(v, __shfl_xor_sync(0xffffffffu, v, 1));
                    v = fmaxf(v, __shfl_xor_sync(0xffffffffu, v, 2));
                    if (tig == 0) sRM[wn*128 + wm*32 + i*16 + grp + h2*8] = v;
                }
            __syncthreads();

            #pragma unroll
            for (int i = 0; i < 2; i++)
                #pragma unroll
                for (int h2 = 0; h2 < 2; h2++) {
                    int row = wm*32 + i*16 + grp + h2*8;
                    float mnew = fmaxf(m_i[i][h2], fmaxf(sRM[row], sRM[128+row]));
                    float fac = __expf(m_i[i][h2] - mnew);
                    m_i[i][h2] = mnew;
                    l_i[i][h2] *= fac;
                    #pragma unroll
                    for (int j = 0; j < 4; j++) {
                        oacc[i][j][h2*2]   *= fac;
                        oacc[i][j][h2*2+1] *= fac;
                    }
                    float rs = 0.0f;
                    #pragma unroll
                    for (int j = 0; j < 8; j++) {
                        float p0 = __expf(sacc[i][j][h2*2]   - mnew);
                        float p1 = __expf(sacc[i][j][h2*2+1] - mnew);
                        rs += p0 + p1;
                        int cu = wn*32 + j*4 + tig;
                        uP[row*68 + cu] = h2_as_u32(__floats2half2_rn(p0, p1));
                    }
                    rs += __shfl_xor_sync(0xffffffffu, rs, 1);
                    rs += __shfl_xor_sync(0xffffffffu, rs, 2);
                    if (tig == 0) sRS[wn*128 + row] = rs;
                }
            __syncthreads();
            #pragma unroll
            for (int i = 0; i < 2; i++)
                #pragma unroll
                for (int h2 = 0; h2 < 2; h2++) {
                    int row = wm*32 + i*16 + grp + h2*8;
                    l_i[i][h2] += sRS[row] + sRS[128 + row];
                }

            #pragma unroll
            for (int ks = 0; ks < 8; ks++) {
                int ko = ks * 8;
                unsigned aF[2][4], bF[4][2];
                #pragma unroll
                for (int j = 0; j < 4; j++) {
                    int n = wn*32 + j*8 + grp;
                    bF[j][0] = uVt[n*68 + ko + tig];
                    bF[j][1] = uVt[n*68 + ko + 4 + tig];
                }
                #pragma unroll
                for (int i = 0; i < 2; i++) {
                    int m = wm*32 + i*16 + grp;
                    aF[i][0] = uP[m*68 + ko + tig];
                    aF[i][1] = uP[(m+8)*68 + ko + tig];
                    aF[i][2] = uP[m*68 + ko + 4 + tig];
                    aF[i][3] = uP[(m+8)*68 + ko + 4 + tig];
                }
                #pragma unroll
                for (int i = 0; i < 2; i++)
                    #pragma unroll
                    for (int j = 0; j < 4; j++)
                        MMA_F16(oacc[i][j], aF[i], bF[j]);
            }
        }

        __half* Ob = Og + (size_t)(b*1024 + qt*128) * 1024 + hh*64;
        #pragma unroll
        for (int i = 0; i < 2; i++)
            #pragma unroll
            for (int h2 = 0; h2 < 2; h2++) {
                int row = wm*32 + i*16 + grp + h2*8;
                float inv = 1.0f / l_i[i][h2];
                #pragma unroll
                for (int j = 0; j < 4; j++) {
                    int col = wn*32 + j*8 + 2*tig;
                    *(__half2*)(Ob + (size_t)row*1024 + col) =
                        __floats2half2_rn(oacc[i][j][h2*2]*inv, oacc[i][j][h2*2+1]*inv);
                }
            }
    }
}

// ---------------- elementwise / small kernels ----------------
__global__ __launch_bounds__(256)
void k_rmsnorm(const float* __restrict__ X, const float* __restrict__ G,
               float* __restrict__ Of, __half* __restrict__ Oh)
{
    int n = blockIdx.x;
    const float4* x4 = (const float4*)(X + (size_t)n * CDIM);
    const float4* g4 = (const float4*)G;
    float4 v = x4[threadIdx.x];
    float ss = v.x*v.x + v.y*v.y + v.z*v.z + v.w*v.w;
    float tot = block_reduce_sum256(ss);
    float r = 1.0f / sqrtf(tot * (1.0f / CDIM) + 1e-6f);
    float4 g = g4[threadIdx.x];
    float4 full = make_float4(v.x*r*g.x, v.y*r*g.y, v.z*r*g.z, v.w*r*g.w);
    if (Of) ((float4*)(Of + (size_t)n * CDIM))[threadIdx.x] = full;
    if (Oh) {
        *(__half2*)(Oh + (size_t)n * CDIM + threadIdx.x * 4)     = __floats2half2_rn(full.x, full.y);
        *(__half2*)(Oh + (size_t)n * CDIM + threadIdx.x * 4 + 2) = __floats2half2_rn(full.z, full.w);
    }
}

__global__ __launch_bounds__(128)
void k_router(const float* __restrict__ HN, const float* __restrict__ WR,
              const float* __restrict__ RB)
{
    int n = blockIdx.x * 4 + (threadIdx.x >> 5);
    int lane = threadIdx.x & 31;
    const float* x = HN + (size_t)n * CDIM;
    float p[NEXP] = {};
    for (int c = lane; c < CDIM; c += 32) {
        float xv = x[c];
        #pragma unroll
        for (int e = 0; e < NEXP; e++) p[e] += xv * WR[c * NEXP + e];
    }
    #pragma unroll
    for (int e = 0; e < NEXP; e++) {
        #pragma unroll
        for (int o = 16; o; o >>= 1)
            p[e] += __shfl_xor_sync(0xffffffffu, p[e], o);
    }
    if (lane == 0) {
        float logit[NEXP], biased[NEXP];
        #pragma unroll
        for (int e = 0; e < NEXP; e++) {
            logit[e]  = p[e] * 0.03125f;
            biased[e] = logit[e] + RB[e];
        }
        int i0 = 0;
        #pragma unroll
        for (int e = 1; e < NEXP; e++) if (biased[e] > biased[i0]) i0 = e;
        int i1 = -1;
        #pragma unroll
        for (int e = 0; e < NEXP; e++) {
            if (e == i0) continue;
            if (i1 < 0 || biased[e] > biased[i1]) i1 = e;
        }
        float m  = fmaxf(logit[i0], logit[i1]);
        float e0 = expf(logit[i0] - m), e1 = expf(logit[i1] - m);
        float inv = 1.0f / (e0 + e1);
        g_top [n*2]     = i0; g_top [n*2 + 1] = i1;
        g_topw[n*2]     = e0 * inv;
        g_topw[n*2 + 1] = e1 * inv;
    }
}

__global__ __launch_bounds__(256)
void k_place()
{
    __shared__ int cnt[NEXP], offp[NEXP], cntp[NEXP], cur[NEXP];
    int tid = threadIdx.x;
    if (tid < NEXP) cnt[tid] = 0;
    __syncthreads();
    for (int i = tid; i < NTOK * 2; i += 256) atomicAdd(&cnt[g_top[i]], 1);
    __syncthreads();
    if (tid == 0) {
        int o = 0;
        for (int e = 0; e < NEXP; e++) {
            offp[e] = o;
            cntp[e] = ((cnt[e] + 127) >> 7) << 7;
            cur[e]  = o;
            g_off_pad[e] = o;
            g_cnt_pad[e] = cntp[e];
            o += cntp[e];
        }
    }
    __syncthreads();
    for (int i = tid; i < NTOK * 2; i += 256) {
        int e = g_top[i];
        int s = atomicAdd(&cur[e], 1);
        g_tok_of_slot[s] = i >> 1;
        g_w_of_slot[s]   = g_topw[i];
        g_slot_of_tok[i] = s;
    }
    __syncthreads();
    for (int e = 0; e < NEXP; e++) {
        int start = offp[e] + cnt[e];
        int end   = offp[e] + cntp[e];
        for (int i = start + tid; i < end; i += 256) {
            g_tok_of_slot[i] = 0;
            g_w_of_slot[i]   = 0.0f;
        }
    }
}

// ---------------- launch ----------------
extern "C" void kernel_launch(void* const* d_in, const int* in_sizes, int n_in,
                              void* d_out, int out_size)
{
    const float* x    = (const float*)d_in[0];
    const float* ga   = (const float*)d_in[1];
    const float* wq   = (const float*)d_in[2];
    const float* wkvd = (const float*)d_in[3];
    const float* wku  = (const float*)d_in[4];
    const float* wvu  = (const float*)d_in[5];
    const float* wo   = (const float*)d_in[6];
    const float* gm   = (const float*)d_in[7];
    const float* wr   = (const float*)d_in[8];
    const float* rb   = (const float*)d_in[9];
    const float* ew1  = (const float*)d_in[10];
    const float* ew2  = (const float*)d_in[11];
    const float* ew3  = (const float*)d_in[12];
    const float* sw1  = (const float*)d_in[13];
    const float* sw2  = (const float*)d_in[14];
    const float* sw3  = (const float*)d_in[15];
    float* out = (float*)d_out;

    float *hb, *hnf;
    __half *xn_h, *q_h, *kv_h, *kvo_h, *att_h, *hn_h, *shid_h;
    __half *wqkv_h, *wkv_h, *wo_h, *sw1_h, *sw3_h, *sw2_h, *ew1_h, *ew2_h, *ew3_h;
    cudaGetSymbolAddress((void**)&hb,   g_h);
    cudaGetSymbolAddress((void**)&hnf,  g_hnf);
    cudaGetSymbolAddress((void**)&xn_h,  g_xn_h);
    cudaGetSymbolAddress((void**)&q_h,   g_q_h);
    cudaGetSymbolAddress((void**)&kv_h,  g_kv_h);
    cudaGetSymbolAddress((void**)&kvo_h, g_kvo_h);
    cudaGetSymbolAddress((void**)&att_h, g_att_h);
    cudaGetSymbolAddress((void**)&hn_h,  g_hn_h);
    cudaGetSymbolAddress((void**)&shid_h, g_shid_h);
    cudaGetSymbolAddress((void**)&wqkv_h, g_wqkv_h);
    cudaGetSymbolAddress((void**)&wkv_h,  g_wkv_h);
    cudaGetSymbolAddress((void**)&wo_h,   g_wo_h);
    cudaGetSymbolAddress((void**)&sw1_h,  g_sw1_h);
    cudaGetSymbolAddress((void**)&sw3_h,  g_sw3_h);
    cudaGetSymbolAddress((void**)&sw2_h,  g_sw2_h);
    cudaGetSymbolAddress((void**)&ew1_h,  g_ew1_h);
    cudaGetSymbolAddress((void**)&ew2_h,  g_ew2_h);
    cudaGetSymbolAddress((void**)&ew3_h,  g_ew3_h);

    cudaFuncSetAttribute(k_flash_h, cudaFuncAttributeMaxDynamicSharedMemorySize, FA_BYTES);
    cudaFuncSetAttribute(gemm_hp<HP_DUAL,64>,     cudaFuncAttributeMaxDynamicSharedMemorySize, SMHP);
    cudaFuncSetAttribute(gemm_hp<HP_EXPDUAL,64>,  cudaFuncAttributeMaxDynamicSharedMemorySize, SMHP);
    cudaFuncSetAttribute(gemm_hp<HP_EXPDOWN,128>, cudaFuncAttributeMaxDynamicSharedMemorySize, SMHP);
    cudaFuncSetAttribute(gemm_hp<HP_RESID,128>,   cudaFuncAttributeMaxDynamicSharedMemorySize, SMHP);
    cudaFuncSetAttribute(gemm_hp<HP_QKV,128>,     cudaFuncAttributeMaxDynamicSharedMemorySize, SMHP);
    cudaFuncSetAttribute(gemm_hp<HP_HALF,128>,    cudaFuncAttributeMaxDynamicSharedMemorySize, SMHP);
    cudaFuncSetAttribute(gemm_hp<HP_FINAL,128>,   cudaFuncAttributeMaxDynamicSharedMemorySize, SMHP);

    // lazily-created side stream + events (host objects only; same work every call)
    static cudaStream_t s1 = nullptr;
    static cudaEvent_t ev_fork = nullptr, ev_join = nullptr;
    if (!s1) {
        cudaStreamCreateWithFlags(&s1, cudaStreamNonBlocking);
        cudaEventCreateWithFlags(&ev_fork, cudaEventDisableTiming);
        cudaEventCreateWithFlags(&ev_join, cudaEventDisableTiming);
    }

    // ---- fork: MoE + wo weight prep on side stream, overlapped with attention ----
    cudaEventRecord(ev_fork, 0);
    cudaStreamWaitEvent(s1, ev_fork, 0);
    k_cvt_tr<<<dim3(32, 32), 256, 0, s1>>>(wo, wo_h, 1024, 1024);
    k_cvt_tr<<<dim3(32, 32, NEXP), 256, 0, s1>>>(ew1, ew1_h, CDIM, FDIM);
    k_cvt_tr<<<dim3(32, 32, NEXP), 256, 0, s1>>>(ew3, ew3_h, CDIM, FDIM);
    k_cvt_tr<<<dim3(32, 32, NEXP), 256, 0, s1>>>(ew2, ew2_h, FDIM, CDIM);
    k_cvt_tr<<<dim3(64, 32), 256, 0, s1>>>(sw1, sw1_h, CDIM, FSH);
    k_cvt_tr<<<dim3(64, 32), 256, 0, s1>>>(sw3, sw3_h, CDIM, FSH);
    k_cvt_tr<<<dim3(32, 64), 256, 0, s1>>>(sw2, sw2_h, FSH, CDIM);
    cudaEventRecord(ev_join, s1);

    // ---- main stream: attention-critical weight prep ----
    k_cvt_tr<<<dim3(32, 32), 256>>>(wq,   wqkv_h,             1024, 1024);
    k_cvt_tr<<<dim3(16, 32), 256>>>(wkvd, wqkv_h + 1024*1024, 1024, 512);
    k_cvt_tr<<<dim3(2, 16), 256>>>(wku,  wkv_h,              512,  64);
    k_cvt_tr<<<dim3(2, 16), 256>>>(wvu,  wkv_h + 64*512,     512,  64);

    // ---- attention (fp16) ----
    k_rmsnorm<<<NTOK, 256>>>(x, ga, nullptr, xn_h);
    gemm_hp<HP_QKV,128><<<dim3(12, 32), 256, SMHP>>>(xn_h, 1024, wqkv_h, nullptr, nullptr, 0, nullptr, 1024);
    gemm_hp<HP_HALF,128><<<dim3(1, 32), 256, SMHP>>>(kv_h, 512, wkv_h, nullptr, kvo_h, 128, nullptr, 512);
    k_flash_h<<<dim3(4, 64), 256, FA_BYTES>>>(q_h, kvo_h, att_h);

    // ---- join: side-stream weight prep must be done before wo / MoE weights used ----
    cudaStreamWaitEvent(0, ev_join, 0);
    gemm_hp<HP_RESID,128><<<dim3(8, 32), 256, SMHP>>>(att_h, 1024, wo_h, nullptr, hb, 1024, x, 1024);

    // ---- MoE (fp16) ----
    k_rmsnorm<<<NTOK, 256>>>(hb, gm, hnf, hn_h);
    k_router<<<NTOK/4, 128>>>(hnf, wr, rb);
    k_place<<<1, 256>>>();
    gemm_hp<HP_EXPDUAL,64><<<dim3(16, 72, NEXP), 256, SMHP>>>(nullptr, 0, ew1_h, ew3_h, nullptr, 0, nullptr, 1024);
    gemm_hp<HP_EXPDOWN,128><<<dim3(8, 72, NEXP), 256, SMHP>>>(nullptr, 0, ew2_h, nullptr, nullptr, 0, nullptr, 1024);
    gemm_hp<HP_DUAL,64><<<dim3(32, 32), 256, SMHP>>>(hn_h, 1024, sw1_h, sw3_h, shid_h, 2048, nullptr, 1024);
    gemm_hp<HP_FINAL,128><<<dim3(8, 32), 256, SMHP>>>(shid_h, 2048, sw2_h, nullptr, out, 1024, hb, 2048);
}